// round 2
// baseline (speedup 1.0000x reference)
#include <cuda_runtime.h>
#include <math.h>

// Sinkhorn on GB300 — matrix-scaling reformulation.
//   E = exp(-C/eps) precomputed once (fp32, __device__ global, 128 MB)
//   iterate: wu = (mu+1e-8)/(E @ wv) ; wv = (nu+1e-8)/(E^T @ wu)
//   pi = E * wu_i * wv_j ; cost = sum(pi*C)
// Batches processed in 2 groups of 4 so the 64 MB E-slice stays L2-resident
// across the 100 passes of that group.

#define P 2048
#define NB 8
#define INV_EPS 10.0f
#define LOG_EPS 1e-8f
#define MAX_ITER 50
#define TOT 33554432   // NB * P * P

__device__ float g_E[TOT];          // exp(-C/eps)
__device__ float g_wu[NB * P];
__device__ float g_wv[NB * P];
__device__ float g_costpart[NB * P];

// ---------------------------------------------------------------- precompute
__global__ void precompute_E(const float* __restrict__ C) {
    size_t stride = (size_t)gridDim.x * blockDim.x;
    const float4* c4 = (const float4*)C;
    float4* e4 = (float4*)g_E;
    for (size_t k = (size_t)blockIdx.x * blockDim.x + threadIdx.x;
         k < (size_t)TOT / 4; k += stride) {
        float4 c = c4[k];
        float4 e;
        e.x = expf(-c.x * INV_EPS);
        e.y = expf(-c.y * INV_EPS);
        e.z = expf(-c.z * INV_EPS);
        e.w = expf(-c.w * INV_EPS);
        e4[k] = e;
    }
}

__global__ void init_wv() {
    int k = blockIdx.x * blockDim.x + threadIdx.x;
    if (k < NB * P) g_wv[k] = 1.0f;
}

// ------------------------------------------------------------- row pass (u)
// one warp per row; reduce over contiguous j. grid: 1024 blocks x 256 thr
// covers 4 batches (group) * 2048 rows = 8192 warps.
__global__ void __launch_bounds__(256) row_pass(const float* __restrict__ mu,
                                                int group) {
    int warp = blockIdx.x * 8 + (threadIdx.x >> 5);
    int lane = threadIdx.x & 31;
    int n = group * 4 + (warp >> 11);
    int i = warp & 2047;

    const float4* e4 = (const float4*)(g_E + ((size_t)n << 22) + ((size_t)i << 11));
    const float4* w4 = (const float4*)(g_wv + (n << 11));

    float a0 = 0.f, a1 = 0.f, a2 = 0.f, a3 = 0.f;
#pragma unroll
    for (int c = 0; c < 16; c++) {
        float4 e = e4[c * 32 + lane];
        float4 w = w4[c * 32 + lane];
        a0 = fmaf(e.x, w.x, a0);
        a1 = fmaf(e.y, w.y, a1);
        a2 = fmaf(e.z, w.z, a2);
        a3 = fmaf(e.w, w.w, a3);
    }
    float s = (a0 + a1) + (a2 + a3);
#pragma unroll
    for (int off = 16; off; off >>= 1)
        s += __shfl_xor_sync(0xffffffffu, s, off);
    if (lane == 0)
        g_wu[(n << 11) + i] = (mu[(n << 11) + i] + LOG_EPS) / s;
}

// ------------------------------------------------------------- col pass (v)
// block = 32 columns x 8 i-slices of 256 rows. Coalesced (lanes span 32
// consecutive columns -> each warp-load is one 128B line). Per-thread private
// accumulators; deterministic shared-memory combine.
// grid: 64 col-tiles * 4 batches = 256 blocks.
__global__ void __launch_bounds__(256) col_pass(const float* __restrict__ nu,
                                                int group) {
    int n = group * 4 + (blockIdx.x >> 6);
    int j0 = (blockIdx.x & 63) * 32;
    int col = threadIdx.x & 31;
    int islice = threadIdx.x >> 5;   // 0..7
    int j = j0 + col;

    const float* ecol = g_E + ((size_t)n << 22) + (size_t)(islice * 256) * P + j;
    const float4* wu4 = (const float4*)(g_wu + (n << 11) + islice * 256);

    float a0 = 0.f, a1 = 0.f, a2 = 0.f, a3 = 0.f;
#pragma unroll 8
    for (int q = 0; q < 64; q++) {
        float4 u = wu4[q];
        const float* ec = ecol + (size_t)q * 4 * P;
        a0 = fmaf(ec[0 * P], u.x, a0);
        a1 = fmaf(ec[1 * P], u.y, a1);
        a2 = fmaf(ec[2 * P], u.z, a2);
        a3 = fmaf(ec[3 * P], u.w, a3);
    }
    __shared__ float part[8][32];
    part[islice][col] = (a0 + a1) + (a2 + a3);
    __syncthreads();
    if (threadIdx.x < 32) {
        float t = 0.f;
#pragma unroll
        for (int k = 0; k < 8; k++) t += part[k][threadIdx.x];
        int jj = j0 + threadIdx.x;
        g_wv[(n << 11) + jj] = (nu[(n << 11) + jj] + LOG_EPS) / t;
    }
}

// ---------------------------------------------------------------- epilogue
// pi = E * wu_i * wv_j ; per-row cost partial (deterministic tree).
// out layout: [cost(8) | pi(TOT) | C(TOT)], guarded by out_size.
__global__ void __launch_bounds__(256) final_pi(const float* __restrict__ C,
                                                float* __restrict__ out,
                                                int out_size) {
    int rowg = blockIdx.x;              // 0..16383
    int n = rowg >> 11, i = rowg & 2047;
    size_t base = ((size_t)n << 22) + ((size_t)i << 11);
    float wui = g_wu[(n << 11) + i];

    const float4* e4 = (const float4*)(g_E + base);
    const float4* c4 = (const float4*)(C + base);
    const float4* w4 = (const float4*)(g_wv + (n << 11));

    bool wpi = out_size >= 8 + TOT;
    bool wc  = out_size >= 8 + 2 * TOT;
    float4* pio = (float4*)(out + 8) + base / 4;
    float4* cco = (float4*)(out + 8 + (size_t)TOT) + base / 4;

    float cl = 0.f;
    for (int k = threadIdx.x; k < 512; k += 256) {
        float4 e = e4[k], c = c4[k], w = w4[k];
        float4 p;
        p.x = e.x * wui * w.x;
        p.y = e.y * wui * w.y;
        p.z = e.z * wui * w.z;
        p.w = e.w * wui * w.w;
        if (wpi) pio[k] = p;
        if (wc)  cco[k] = c;
        cl = fmaf(p.x, c.x, fmaf(p.y, c.y, fmaf(p.z, c.z, fmaf(p.w, c.w, cl))));
    }
    __shared__ float red[256];
    red[threadIdx.x] = cl;
    __syncthreads();
    for (int s2 = 128; s2 > 0; s2 >>= 1) {
        if (threadIdx.x < s2) red[threadIdx.x] += red[threadIdx.x + s2];
        __syncthreads();
    }
    if (threadIdx.x == 0) g_costpart[rowg] = red[0];
}

__global__ void cost_combine(float* __restrict__ out, int out_size) {
    int n = blockIdx.x;
    __shared__ float red[256];
    const float* p = g_costpart + (n << 11);
    float s = 0.f;
    for (int k = threadIdx.x; k < P; k += 256) s += p[k];
    red[threadIdx.x] = s;
    __syncthreads();
    for (int s2 = 128; s2 > 0; s2 >>= 1) {
        if (threadIdx.x < s2) red[threadIdx.x] += red[threadIdx.x + s2];
        __syncthreads();
    }
    if (threadIdx.x == 0 && out_size > n) out[n] = red[0];
}

// ------------------------------------------------------------------ launch
extern "C" void kernel_launch(void* const* d_in, const int* in_sizes, int n_in,
                              void* d_out, int out_size) {
    const float* C  = (const float*)d_in[0];
    const float* mu = (const float*)d_in[1];
    const float* nu = (const float*)d_in[2];
    float* out = (float*)d_out;

    precompute_E<<<4096, 256>>>(C);
    init_wv<<<64, 256>>>();

    // 2 groups of 4 batches: 64 MB E-slice stays L2-resident across the
    // group's 100 passes.
    for (int g = 0; g < 2; g++) {
        for (int it = 0; it < MAX_ITER; it++) {
            row_pass<<<1024, 256>>>(mu, g);
            col_pass<<<256, 256>>>(nu, g);
        }
    }

    final_pi<<<16384, 256>>>(C, out, out_size);
    cost_combine<<<8, 256>>>(out, out_size);
}

// round 6
// speedup vs baseline: 1.1828x; 1.1828x over previous
#include <cuda_runtime.h>
#include <cuda_fp16.h>
#include <math.h>

// Sinkhorn on GB300 — matrix-scaling reformulation, fp16 kernel matrix.
//   Eh = exp(-C/eps) precomputed once in fp16 (64 MB -> entire E is L2-resident)
//   iterate: wu = (mu+1e-8)/(E @ wv) ; wv = (nu+1e-8)/(E^T @ wu)   [fp32 accum]
//   pi = E * wu_i * wv_j ; cost = sum(pi*C)
// All 8 batches per pass (E fits in the 126 MB L2); 104 total graph nodes.

#define P 2048
#define NB 8
#define INV_EPS 10.0f
#define LOG_EPS 1e-8f
#define MAX_ITER 50
#define TOT 33554432   // NB * P * P

__device__ __half g_Eh[TOT];        // exp(-C/eps), fp16
__device__ float g_wu[NB * P];
__device__ float g_wv[NB * P];
__device__ float g_costpart[NB * P];

__device__ __forceinline__ float2 h2f(unsigned int u) {
    __half2 h = *reinterpret_cast<__half2*>(&u);
    return __half22float2(h);
}

// ---------------------------------------------------------------- precompute
// thread handles 8 elems: read 2 float4 of C, write 1 int4 (8 halves).
__global__ void precompute_E(const float* __restrict__ C) {
    size_t stride = (size_t)gridDim.x * blockDim.x;
    const float4* c4 = (const float4*)C;
    int4* e4 = (int4*)g_Eh;
    for (size_t k = (size_t)blockIdx.x * blockDim.x + threadIdx.x;
         k < (size_t)TOT / 8; k += stride) {
        float4 a = c4[2 * k], b = c4[2 * k + 1];
        __half2 h0 = __floats2half2_rn(expf(-a.x * INV_EPS), expf(-a.y * INV_EPS));
        __half2 h1 = __floats2half2_rn(expf(-a.z * INV_EPS), expf(-a.w * INV_EPS));
        __half2 h2 = __floats2half2_rn(expf(-b.x * INV_EPS), expf(-b.y * INV_EPS));
        __half2 h3 = __floats2half2_rn(expf(-b.z * INV_EPS), expf(-b.w * INV_EPS));
        int4 o;
        o.x = *reinterpret_cast<int*>(&h0);
        o.y = *reinterpret_cast<int*>(&h1);
        o.z = *reinterpret_cast<int*>(&h2);
        o.w = *reinterpret_cast<int*>(&h3);
        e4[k] = o;
    }
}

__global__ void init_wv() {
    int k = blockIdx.x * blockDim.x + threadIdx.x;
    if (k < NB * P) g_wv[k] = 1.0f;
}

// ------------------------------------------------------------- row pass (u)
// one warp per row (all 8 batches): 16384 warps -> grid 2048 x 256.
// lane reads int4 = 8 halves per step, 8 steps covers the 2048-elem row.
__global__ void __launch_bounds__(256) row_pass(const float* __restrict__ mu) {
    int warp = blockIdx.x * 8 + (threadIdx.x >> 5);
    int lane = threadIdx.x & 31;
    int n = warp >> 11;
    int i = warp & 2047;

    const int4* e4 = (const int4*)(g_Eh + ((size_t)n << 22) + ((size_t)i << 11));
    const float4* w4 = (const float4*)(g_wv + (n << 11));

    float a0 = 0.f, a1 = 0.f, a2 = 0.f, a3 = 0.f;
#pragma unroll
    for (int c = 0; c < 8; c++) {
        int idx = c * 32 + lane;          // int4 index, covers halves 8*idx..8*idx+7
        int4 r = e4[idx];
        float4 wA = w4[2 * idx];
        float4 wB = w4[2 * idx + 1];
        float2 f0 = h2f((unsigned)r.x);
        float2 f1 = h2f((unsigned)r.y);
        float2 f2 = h2f((unsigned)r.z);
        float2 f3 = h2f((unsigned)r.w);
        a0 = fmaf(f0.x, wA.x, a0); a1 = fmaf(f0.y, wA.y, a1);
        a2 = fmaf(f1.x, wA.z, a2); a3 = fmaf(f1.y, wA.w, a3);
        a0 = fmaf(f2.x, wB.x, a0); a1 = fmaf(f2.y, wB.y, a1);
        a2 = fmaf(f3.x, wB.z, a2); a3 = fmaf(f3.y, wB.w, a3);
    }
    float s = (a0 + a1) + (a2 + a3);
#pragma unroll
    for (int off = 16; off; off >>= 1)
        s += __shfl_xor_sync(0xffffffffu, s, off);
    if (lane == 0)
        g_wu[(n << 11) + i] = (mu[(n << 11) + i] + LOG_EPS) / s;
}

// ------------------------------------------------------------- col pass (v)
// block = 64 columns x 8 i-slices of 256 rows. Each lane owns a half2
// (2 adjacent columns) -> warp spans 64 consecutive halves = full 128B line.
// grid: 32 col-tiles * 8 batches = 256 blocks x 256 thr.
__global__ void __launch_bounds__(256) col_pass(const float* __restrict__ nu) {
    int n = blockIdx.x >> 5;
    int j0 = (blockIdx.x & 31) * 64;
    int lane = threadIdx.x & 31;
    int islice = threadIdx.x >> 5;    // 0..7

    const __half* base = g_Eh + ((size_t)n << 22)
                              + (size_t)(islice * 256) * P + j0 + lane * 2;
    const float4* wu4 = (const float4*)(g_wu + (n << 11) + islice * 256);

    float ax = 0.f, ay = 0.f, bx = 0.f, by = 0.f;
#pragma unroll 8
    for (int q = 0; q < 64; q++) {
        float4 u = wu4[q];
        const __half* b0 = base + (size_t)(4 * q) * P;
        float2 e0 = __half22float2(*(const __half2*)(b0));
        float2 e1 = __half22float2(*(const __half2*)(b0 + P));
        float2 e2 = __half22float2(*(const __half2*)(b0 + 2 * P));
        float2 e3 = __half22float2(*(const __half2*)(b0 + 3 * P));
        ax = fmaf(e0.x, u.x, ax); ay = fmaf(e0.y, u.x, ay);
        bx = fmaf(e1.x, u.y, bx); by = fmaf(e1.y, u.y, by);
        ax = fmaf(e2.x, u.z, ax); ay = fmaf(e2.y, u.z, ay);
        bx = fmaf(e3.x, u.w, bx); by = fmaf(e3.y, u.w, by);
    }
    __shared__ float part[8][64];
    part[islice][lane * 2]     = ax + bx;
    part[islice][lane * 2 + 1] = ay + by;
    __syncthreads();
    if (threadIdx.x < 64) {
        float t = 0.f;
#pragma unroll
        for (int k = 0; k < 8; k++) t += part[k][threadIdx.x];
        int jj = j0 + threadIdx.x;
        g_wv[(n << 11) + jj] = (nu[(n << 11) + jj] + LOG_EPS) / t;
    }
}

// ---------------------------------------------------------------- epilogue
// pi = E * wu_i * wv_j ; per-row cost partial (deterministic tree).
// out layout: [cost(8) | pi(TOT) | C(TOT)], guarded by out_size.
__global__ void __launch_bounds__(256) final_pi(const float* __restrict__ C,
                                                float* __restrict__ out,
                                                int out_size) {
    int rowg = blockIdx.x;              // 0..16383
    int n = rowg >> 11, i = rowg & 2047;
    size_t base = ((size_t)n << 22) + ((size_t)i << 11);
    float wui = g_wu[(n << 11) + i];

    const int4* e4 = (const int4*)(g_Eh + base);     // 256 int4 per row
    const float4* c4 = (const float4*)(C + base);
    const float4* w4 = (const float4*)(g_wv + (n << 11));

    bool wpi = out_size >= 8 + TOT;
    bool wc  = out_size >= 8 + 2 * TOT;
    float4* pio = (float4*)(out + 8) + base / 4;
    float4* cco = (float4*)(out + 8 + (size_t)TOT) + base / 4;

    // thread handles 8 elems: 1 int4 E, 2 float4 C, 2 float4 pi out, 2 C out.
    int t = threadIdx.x;
    int4 r = e4[t];
    float4 cA = c4[2 * t], cB = c4[2 * t + 1];
    float4 wA = w4[2 * t], wB = w4[2 * t + 1];
    float2 f0 = h2f((unsigned)r.x);
    float2 f1 = h2f((unsigned)r.y);
    float2 f2 = h2f((unsigned)r.z);
    float2 f3 = h2f((unsigned)r.w);
    float4 pA, pB;
    pA.x = f0.x * wui * wA.x;  pA.y = f0.y * wui * wA.y;
    pA.z = f1.x * wui * wA.z;  pA.w = f1.y * wui * wA.w;
    pB.x = f2.x * wui * wB.x;  pB.y = f2.y * wui * wB.y;
    pB.z = f3.x * wui * wB.z;  pB.w = f3.y * wui * wB.w;
    if (wpi) { pio[2 * t] = pA; pio[2 * t + 1] = pB; }
    if (wc)  { cco[2 * t] = cA; cco[2 * t + 1] = cB; }
    float cl = 0.f;
    cl = fmaf(pA.x, cA.x, fmaf(pA.y, cA.y, fmaf(pA.z, cA.z, fmaf(pA.w, cA.w, cl))));
    cl = fmaf(pB.x, cB.x, fmaf(pB.y, cB.y, fmaf(pB.z, cB.z, fmaf(pB.w, cB.w, cl))));

    __shared__ float red[256];
    red[t] = cl;
    __syncthreads();
    for (int s2 = 128; s2 > 0; s2 >>= 1) {
        if (t < s2) red[t] += red[t + s2];
        __syncthreads();
    }
    if (t == 0) g_costpart[rowg] = red[0];
}

__global__ void cost_combine(float* __restrict__ out, int out_size) {
    int n = blockIdx.x;
    __shared__ float red[256];
    const float* p = g_costpart + (n << 11);
    float s = 0.f;
    for (int k = threadIdx.x; k < P; k += 256) s += p[k];
    red[threadIdx.x] = s;
    __syncthreads();
    for (int s2 = 128; s2 > 0; s2 >>= 1) {
        if (threadIdx.x < s2) red[threadIdx.x] += red[threadIdx.x + s2];
        __syncthreads();
    }
    if (threadIdx.x == 0 && out_size > n) out[n] = red[0];
}

// ------------------------------------------------------------------ launch
extern "C" void kernel_launch(void* const* d_in, const int* in_sizes, int n_in,
                              void* d_out, int out_size) {
    const float* C  = (const float*)d_in[0];
    const float* mu = (const float*)d_in[1];
    const float* nu = (const float*)d_in[2];
    float* out = (float*)d_out;

    precompute_E<<<4096, 256>>>(C);
    init_wv<<<64, 256>>>();

    // fp16 E = 64 MB total -> stays L2-resident across all 100 passes.
    for (int it = 0; it < MAX_ITER; it++) {
        row_pass<<<2048, 256>>>(mu);
        col_pass<<<256, 256>>>(nu);
    }

    final_pi<<<16384, 256>>>(C, out, out_size);
    cost_combine<<<8, 256>>>(out, out_size);
}

// round 7
// speedup vs baseline: 1.6884x; 1.4274x over previous
#include <cuda_runtime.h>
#include <cuda_fp16.h>
#include <math.h>

// Sinkhorn on GB300 — fused matrix-scaling iteration.
//   Eh = exp(-C/eps) in fp16 (64 MB, L2-resident).
//   Each iteration is ONE read of E: warp computes row dot (E @ wv), gets
//   wu_i in-register, immediately accumulates column partials E_ij*wu_i
//   from the same registers. Column partials combined by a small kernel.
//   pi = E * wu_i * wv_j ; cost = sum(pi*C).

#define P 2048
#define NB 8
#define INV_EPS 10.0f
#define LOG_EPS 1e-8f
#define MAX_ITER 50
#define TOT 33554432           // NB * P * P
#define WPB 128                // warp-partials per batch (16 blocks * 8 warps)

__device__ __half g_Eh[TOT];
__device__ float g_wu[NB * P];
__device__ float g_wv[NB * P];
__device__ float g_part[NB * WPB * P];   // 8 MB column partials
__device__ float g_costpart[NB * P];

__device__ __forceinline__ float2 h2f(unsigned int u) {
    __half2 h = *reinterpret_cast<__half2*>(&u);
    return __half22float2(h);
}

// ---------------------------------------------------------------- precompute
__global__ void precompute_E(const float* __restrict__ C) {
    size_t stride = (size_t)gridDim.x * blockDim.x;
    const float4* c4 = (const float4*)C;
    int4* e4 = (int4*)g_Eh;
    for (size_t k = (size_t)blockIdx.x * blockDim.x + threadIdx.x;
         k < (size_t)TOT / 8; k += stride) {
        float4 a = c4[2 * k], b = c4[2 * k + 1];
        __half2 h0 = __floats2half2_rn(expf(-a.x * INV_EPS), expf(-a.y * INV_EPS));
        __half2 h1 = __floats2half2_rn(expf(-a.z * INV_EPS), expf(-a.w * INV_EPS));
        __half2 h2 = __floats2half2_rn(expf(-b.x * INV_EPS), expf(-b.y * INV_EPS));
        __half2 h3 = __floats2half2_rn(expf(-b.z * INV_EPS), expf(-b.w * INV_EPS));
        int4 o;
        o.x = *reinterpret_cast<int*>(&h0);
        o.y = *reinterpret_cast<int*>(&h1);
        o.z = *reinterpret_cast<int*>(&h2);
        o.w = *reinterpret_cast<int*>(&h3);
        e4[k] = o;
    }
}

__global__ void init_wv() {
    int k = blockIdx.x * blockDim.x + threadIdx.x;
    if (k < NB * P) g_wv[k] = 1.0f;
}

// --------------------------------------------------------------- fused pass
// grid = 128 blocks (8 batches x 16 row-blocks), 256 thr (8 warps).
// warp handles 16 rows. lane owns 64 fixed columns: col = 256c + 8*lane + h,
// (c=0..7, h=0..7), i.e. one int4 (8 halves) per c-step. wv for a lane's
// columns is staged in smem permuted as wvp[k][lane] (conflict-free LDS.32).
__global__ void __launch_bounds__(256) fused_pass(const float* __restrict__ mu) {
    int n = blockIdx.x >> 4;
    int rblk = blockIdx.x & 15;
    int wid = threadIdx.x >> 5;
    int lane = threadIdx.x & 31;

    __shared__ float wvp[64][32];                 // 8 KB, [k][lane]
    const float* wvb = g_wv + (n << 11);
    for (int idx = threadIdx.x; idx < P; idx += 256) {
        int c = idx >> 8, h = idx & 7, l = (idx >> 3) & 31;
        wvp[c * 8 + h][l] = wvb[idx];
    }
    __syncthreads();

    float acc[64];
#pragma unroll
    for (int k = 0; k < 64; k++) acc[k] = 0.f;

    const int4* Eb = (const int4*)(g_Eh + ((size_t)n << 22));
    const float* mub = mu + (n << 11);
    int i0 = rblk * 128 + wid * 16;

    for (int r = 0; r < 16; r++) {
        int i = i0 + r;
        const int4* e4 = Eb + ((size_t)i << 8);   // 256 int4 per row

        // load + unpack this lane's 64 E values (8 independent LDG.128)
        float ef[64];
#pragma unroll
        for (int c = 0; c < 8; c++) {
            int4 e = e4[c * 32 + lane];
            float2 f0 = h2f((unsigned)e.x);
            float2 f1 = h2f((unsigned)e.y);
            float2 f2 = h2f((unsigned)e.z);
            float2 f3 = h2f((unsigned)e.w);
            ef[c * 8 + 0] = f0.x; ef[c * 8 + 1] = f0.y;
            ef[c * 8 + 2] = f1.x; ef[c * 8 + 3] = f1.y;
            ef[c * 8 + 4] = f2.x; ef[c * 8 + 5] = f2.y;
            ef[c * 8 + 6] = f3.x; ef[c * 8 + 7] = f3.y;
        }

        // row dot with wv
        float s0 = 0.f, s1 = 0.f, s2 = 0.f, s3 = 0.f;
#pragma unroll
        for (int k = 0; k < 64; k += 4) {
            s0 = fmaf(ef[k + 0], wvp[k + 0][lane], s0);
            s1 = fmaf(ef[k + 1], wvp[k + 1][lane], s1);
            s2 = fmaf(ef[k + 2], wvp[k + 2][lane], s2);
            s3 = fmaf(ef[k + 3], wvp[k + 3][lane], s3);
        }
        float s = (s0 + s1) + (s2 + s3);
#pragma unroll
        for (int off = 16; off; off >>= 1)
            s += __shfl_xor_sync(0xffffffffu, s, off);

        float wu = (mub[i] + LOG_EPS) / s;
        if (lane == 0) g_wu[(n << 11) + i] = wu;

        // column accumulation from the SAME registers (no extra E traffic)
#pragma unroll
        for (int k = 0; k < 64; k++)
            acc[k] = fmaf(ef[k], wu, acc[k]);
    }

    // write this warp's 2048 column partials (contiguous float4s)
    int w = rblk * 8 + wid;
    float* pp = g_part + ((size_t)n << 18) + (w << 11);
#pragma unroll
    for (int c = 0; c < 8; c++) {
        float4 A = make_float4(acc[c * 8 + 0], acc[c * 8 + 1],
                               acc[c * 8 + 2], acc[c * 8 + 3]);
        float4 B = make_float4(acc[c * 8 + 4], acc[c * 8 + 5],
                               acc[c * 8 + 6], acc[c * 8 + 7]);
        *(float4*)(pp + 256 * c + 8 * lane)     = A;
        *(float4*)(pp + 256 * c + 8 * lane + 4) = B;
    }
}

// ------------------------------------------------------------- col combine
// one thread per (n, j): sum 128 warp partials in fixed order -> wv update.
__global__ void __launch_bounds__(256) col_combine(const float* __restrict__ nu) {
    int gid = blockIdx.x * 256 + threadIdx.x;     // 0..16383
    int n = gid >> 11, j = gid & 2047;
    const float* pp = g_part + ((size_t)n << 18) + j;
    float t0 = 0.f, t1 = 0.f, t2 = 0.f, t3 = 0.f;
#pragma unroll 8
    for (int w = 0; w < WPB; w += 4) {
        t0 += pp[(size_t)(w + 0) << 11];
        t1 += pp[(size_t)(w + 1) << 11];
        t2 += pp[(size_t)(w + 2) << 11];
        t3 += pp[(size_t)(w + 3) << 11];
    }
    float t = (t0 + t1) + (t2 + t3);
    g_wv[gid] = (nu[gid] + LOG_EPS) / t;
}

// ---------------------------------------------------------------- epilogue
// pi = E * wu_i * wv_j ; per-row cost partial (deterministic tree).
// out layout: [cost(8) | pi(TOT) | C(TOT)], guarded by out_size.
__global__ void __launch_bounds__(256) final_pi(const float* __restrict__ C,
                                                float* __restrict__ out,
                                                int out_size) {
    int rowg = blockIdx.x;              // 0..16383
    int n = rowg >> 11, i = rowg & 2047;
    size_t base = ((size_t)n << 22) + ((size_t)i << 11);
    float wui = g_wu[(n << 11) + i];

    const int4* e4 = (const int4*)(g_Eh + base);
    const float4* c4 = (const float4*)(C + base);
    const float4* w4 = (const float4*)(g_wv + (n << 11));

    bool wpi = out_size >= 8 + TOT;
    bool wc  = out_size >= 8 + 2 * TOT;
    float4* pio = (float4*)(out + 8) + base / 4;
    float4* cco = (float4*)(out + 8 + (size_t)TOT) + base / 4;

    int t = threadIdx.x;
    int4 r = e4[t];
    float4 cA = c4[2 * t], cB = c4[2 * t + 1];
    float4 wA = w4[2 * t], wB = w4[2 * t + 1];
    float2 f0 = h2f((unsigned)r.x);
    float2 f1 = h2f((unsigned)r.y);
    float2 f2 = h2f((unsigned)r.z);
    float2 f3 = h2f((unsigned)r.w);
    float4 pA, pB;
    pA.x = f0.x * wui * wA.x;  pA.y = f0.y * wui * wA.y;
    pA.z = f1.x * wui * wA.z;  pA.w = f1.y * wui * wA.w;
    pB.x = f2.x * wui * wB.x;  pB.y = f2.y * wui * wB.y;
    pB.z = f3.x * wui * wB.z;  pB.w = f3.y * wui * wB.w;
    if (wpi) { pio[2 * t] = pA; pio[2 * t + 1] = pB; }
    if (wc)  { cco[2 * t] = cA; cco[2 * t + 1] = cB; }
    float cl = 0.f;
    cl = fmaf(pA.x, cA.x, fmaf(pA.y, cA.y, fmaf(pA.z, cA.z, fmaf(pA.w, cA.w, cl))));
    cl = fmaf(pB.x, cB.x, fmaf(pB.y, cB.y, fmaf(pB.z, cB.z, fmaf(pB.w, cB.w, cl))));

    __shared__ float red[256];
    red[t] = cl;
    __syncthreads();
    for (int s2 = 128; s2 > 0; s2 >>= 1) {
        if (t < s2) red[t] += red[t + s2];
        __syncthreads();
    }
    if (t == 0) g_costpart[rowg] = red[0];
}

__global__ void cost_combine(float* __restrict__ out, int out_size) {
    int n = blockIdx.x;
    __shared__ float red[256];
    const float* p = g_costpart + (n << 11);
    float s = 0.f;
    for (int k = threadIdx.x; k < P; k += 256) s += p[k];
    red[threadIdx.x] = s;
    __syncthreads();
    for (int s2 = 128; s2 > 0; s2 >>= 1) {
        if (threadIdx.x < s2) red[threadIdx.x] += red[threadIdx.x + s2];
        __syncthreads();
    }
    if (threadIdx.x == 0 && out_size > n) out[n] = red[0];
}

// ------------------------------------------------------------------ launch
extern "C" void kernel_launch(void* const* d_in, const int* in_sizes, int n_in,
                              void* d_out, int out_size) {
    const float* C  = (const float*)d_in[0];
    const float* mu = (const float*)d_in[1];
    const float* nu = (const float*)d_in[2];
    float* out = (float*)d_out;

    precompute_E<<<4096, 256>>>(C);
    init_wv<<<64, 256>>>();

    for (int it = 0; it < MAX_ITER; it++) {
        fused_pass<<<128, 256>>>(mu);     // one E read per iteration
        col_combine<<<64, 256>>>(nu);
    }

    final_pi<<<16384, 256>>>(C, out, out_size);
    cost_combine<<<8, 256>>>(out, out_size);
}

// round 8
// speedup vs baseline: 1.7709x; 1.0489x over previous
#include <cuda_runtime.h>
#include <cuda_fp16.h>
#include <math.h>

// Sinkhorn on GB300 — single persistent kernel with device-wide barrier.
//   Eh = exp(-C/eps) in fp16 (64 MB, L2-resident).
//   Per iteration: warp computes row dot (E @ wv) -> wu in-register ->
//   column partials from same registers -> block-level smem reduce (16
//   block-partials/batch) -> grid barrier -> distributed combine -> barrier.
//   pi = E * wu_i * wv_j ; cost = sum(pi*C).

#define P 2048
#define NB 8
#define INV_EPS 10.0f
#define LOG_EPS 1e-8f
#define MAX_ITER 50
#define TOT 33554432           // NB * P * P
#define NBLK 128               // 8 batches x 16 row-blocks; <=148 SMs -> co-resident

__device__ __half g_Eh[TOT];
__device__ float g_wu[NB * P];
__device__ float g_wv[NB * P];
__device__ float g_bpart[NB * 16 * P];   // 1 MB block partials
__device__ float g_costpart[NB * P];

__device__ unsigned g_arrive;            // zero-init
__device__ volatile unsigned g_gen;      // generation counter (wraps; equality-based)

__device__ __forceinline__ float2 h2f(unsigned int u) {
    __half2 h = *reinterpret_cast<__half2*>(&u);
    return __half22float2(h);
}

// sense-reversing grid barrier; all NBLK blocks co-resident (1 block/SM).
__device__ __forceinline__ void grid_sync() {
    __syncthreads();
    if (threadIdx.x == 0) {
        unsigned g = g_gen;
        __threadfence();                       // release (drains stores, CCTL.IVALL)
        if (atomicAdd(&g_arrive, 1u) == NBLK - 1) {
            g_arrive = 0;                      // unique last arriver
            __threadfence();
            g_gen = g + 1;
        } else {
            while (g_gen == g) __nanosleep(64);
        }
        __threadfence();                       // acquire (invalidate stale L1)
    }
    __syncthreads();
}

// ---------------------------------------------------------------- precompute
__global__ void precompute_E(const float* __restrict__ C) {
    size_t stride = (size_t)gridDim.x * blockDim.x;
    const float4* c4 = (const float4*)C;
    int4* e4 = (int4*)g_Eh;
    for (size_t k = (size_t)blockIdx.x * blockDim.x + threadIdx.x;
         k < (size_t)TOT / 8; k += stride) {
        float4 a = c4[2 * k], b = c4[2 * k + 1];
        __half2 h0 = __floats2half2_rn(expf(-a.x * INV_EPS), expf(-a.y * INV_EPS));
        __half2 h1 = __floats2half2_rn(expf(-a.z * INV_EPS), expf(-a.w * INV_EPS));
        __half2 h2 = __floats2half2_rn(expf(-b.x * INV_EPS), expf(-b.y * INV_EPS));
        __half2 h3 = __floats2half2_rn(expf(-b.z * INV_EPS), expf(-b.w * INV_EPS));
        int4 o;
        o.x = *reinterpret_cast<int*>(&h0);
        o.y = *reinterpret_cast<int*>(&h1);
        o.z = *reinterpret_cast<int*>(&h2);
        o.w = *reinterpret_cast<int*>(&h3);
        e4[k] = o;
    }
}

// --------------------------------------------------------- persistent kernel
// block = (n, rblk): batch n, rows [rblk*128, rblk*128+128). 8 warps x 16 rows.
// lane owns 64 fixed columns: col = 256c + 8*lane + h (c=0..7, h=0..7).
__global__ void __launch_bounds__(256) sinkhorn_persist(const float* __restrict__ mu,
                                                        const float* __restrict__ nu) {
    int n = blockIdx.x >> 4;
    int rblk = blockIdx.x & 15;
    int wid = threadIdx.x >> 5;
    int lane = threadIdx.x & 31;

    __shared__ float wvp[64][32];     // 8 KB permuted wv  [k][lane]
    __shared__ float red[8][512];     // 16 KB block-reduce staging
    __shared__ float mus[128];        // this block's mu rows

    if (threadIdx.x < 128)
        mus[threadIdx.x] = mu[(n << 11) + rblk * 128 + threadIdx.x];

    int gid = blockIdx.x * 256 + threadIdx.x;     // 0..32767
    float nuv = 0.f;
    if (gid < NB * P) {
        nuv = nu[gid] + LOG_EPS;
        g_wv[gid] = 1.0f;                          // init wv
    }
    grid_sync();

    const int4* Eb = (const int4*)(g_Eh + ((size_t)n << 22));
    const float* wvb = g_wv + (n << 11);
    int i0 = rblk * 128 + wid * 16;

    for (int it = 0; it < MAX_ITER; it++) {
        // stage wv permuted for conflict-free LDS
        for (int idx = threadIdx.x; idx < P; idx += 256) {
            int c = idx >> 8, h = idx & 7, l = (idx >> 3) & 31;
            wvp[c * 8 + h][l] = wvb[idx];
        }
        __syncthreads();

        float acc[64];
#pragma unroll
        for (int k = 0; k < 64; k++) acc[k] = 0.f;

        for (int r = 0; r < 16; r++) {
            int i = i0 + r;
            const int4* e4 = Eb + ((size_t)i << 8);

            float ef[64];
#pragma unroll
            for (int c = 0; c < 8; c++) {
                int4 e = e4[c * 32 + lane];
                float2 f0 = h2f((unsigned)e.x);
                float2 f1 = h2f((unsigned)e.y);
                float2 f2 = h2f((unsigned)e.z);
                float2 f3 = h2f((unsigned)e.w);
                ef[c * 8 + 0] = f0.x; ef[c * 8 + 1] = f0.y;
                ef[c * 8 + 2] = f1.x; ef[c * 8 + 3] = f1.y;
                ef[c * 8 + 4] = f2.x; ef[c * 8 + 5] = f2.y;
                ef[c * 8 + 6] = f3.x; ef[c * 8 + 7] = f3.y;
            }

            float s0 = 0.f, s1 = 0.f, s2 = 0.f, s3 = 0.f;
#pragma unroll
            for (int k = 0; k < 64; k += 4) {
                s0 = fmaf(ef[k + 0], wvp[k + 0][lane], s0);
                s1 = fmaf(ef[k + 1], wvp[k + 1][lane], s1);
                s2 = fmaf(ef[k + 2], wvp[k + 2][lane], s2);
                s3 = fmaf(ef[k + 3], wvp[k + 3][lane], s3);
            }
            float s = (s0 + s1) + (s2 + s3);
#pragma unroll
            for (int off = 16; off; off >>= 1)
                s += __shfl_xor_sync(0xffffffffu, s, off);

            float wu = (mus[wid * 16 + r] + LOG_EPS) / s;
            if (lane == 0) g_wu[(n << 11) + i] = wu;

#pragma unroll
            for (int k = 0; k < 64; k++)
                acc[k] = fmaf(ef[k], wu, acc[k]);
        }

        // block-level reduce of column partials: 4 chunks of 512 columns
        float* bp = g_bpart + ((size_t)(n * 16 + rblk) << 11);
#pragma unroll
        for (int chunk = 0; chunk < 4; chunk++) {
            __syncthreads();                       // red reusable
#pragma unroll
            for (int cp = 0; cp < 2; cp++)
#pragma unroll
                for (int h = 0; h < 8; h++)
                    red[wid][cp * 256 + lane * 8 + h] = acc[(2 * chunk + cp) * 8 + h];
            __syncthreads();
#pragma unroll
            for (int t = threadIdx.x; t < 512; t += 256) {
                float v = 0.f;
#pragma unroll
                for (int w = 0; w < 8; w++) v += red[w][t];
                bp[chunk * 512 + t] = v;
            }
        }

        grid_sync();                               // all block partials visible

        // distributed combine: 1 thread per (n,j)
        if (gid < NB * P) {
            int nn = gid >> 11, j = gid & 2047;
            const float* pp = g_bpart + ((size_t)(nn * 16) << 11) + j;
            float t0 = 0.f, t1 = 0.f, t2 = 0.f, t3 = 0.f;
#pragma unroll
            for (int b = 0; b < 16; b += 4) {
                t0 += pp[(size_t)(b + 0) << 11];
                t1 += pp[(size_t)(b + 1) << 11];
                t2 += pp[(size_t)(b + 2) << 11];
                t3 += pp[(size_t)(b + 3) << 11];
            }
            g_wv[gid] = nuv / ((t0 + t1) + (t2 + t3));
        }

        grid_sync();                               // wv complete for next iter
    }
}

// ---------------------------------------------------------------- epilogue
// pi = E * wu_i * wv_j ; per-row cost partial (deterministic tree).
// out layout: [cost(8) | pi(TOT) | C(TOT)], guarded by out_size.
__global__ void __launch_bounds__(256) final_pi(const float* __restrict__ C,
                                                float* __restrict__ out,
                                                int out_size) {
    int rowg = blockIdx.x;              // 0..16383
    int n = rowg >> 11, i = rowg & 2047;
    size_t base = ((size_t)n << 22) + ((size_t)i << 11);
    float wui = g_wu[(n << 11) + i];

    const int4* e4 = (const int4*)(g_Eh + base);
    const float4* c4 = (const float4*)(C + base);
    const float4* w4 = (const float4*)(g_wv + (n << 11));

    bool wpi = out_size >= 8 + TOT;
    bool wc  = out_size >= 8 + 2 * TOT;
    float4* pio = (float4*)(out + 8) + base / 4;
    float4* cco = (float4*)(out + 8 + (size_t)TOT) + base / 4;

    int t = threadIdx.x;
    int4 r = e4[t];
    float4 cA = c4[2 * t], cB = c4[2 * t + 1];
    float4 wA = w4[2 * t], wB = w4[2 * t + 1];
    float2 f0 = h2f((unsigned)r.x);
    float2 f1 = h2f((unsigned)r.y);
    float2 f2 = h2f((unsigned)r.z);
    float2 f3 = h2f((unsigned)r.w);
    float4 pA, pB;
    pA.x = f0.x * wui * wA.x;  pA.y = f0.y * wui * wA.y;
    pA.z = f1.x * wui * wA.z;  pA.w = f1.y * wui * wA.w;
    pB.x = f2.x * wui * wB.x;  pB.y = f2.y * wui * wB.y;
    pB.z = f3.x * wui * wB.z;  pB.w = f3.y * wui * wB.w;
    if (wpi) { pio[2 * t] = pA; pio[2 * t + 1] = pB; }
    if (wc)  { cco[2 * t] = cA; cco[2 * t + 1] = cB; }
    float cl = 0.f;
    cl = fmaf(pA.x, cA.x, fmaf(pA.y, cA.y, fmaf(pA.z, cA.z, fmaf(pA.w, cA.w, cl))));
    cl = fmaf(pB.x, cB.x, fmaf(pB.y, cB.y, fmaf(pB.z, cB.z, fmaf(pB.w, cB.w, cl))));

    __shared__ float red[256];
    red[t] = cl;
    __syncthreads();
    for (int s2 = 128; s2 > 0; s2 >>= 1) {
        if (t < s2) red[t] += red[t + s2];
        __syncthreads();
    }
    if (t == 0) g_costpart[rowg] = red[0];
}

__global__ void cost_combine(float* __restrict__ out, int out_size) {
    int n = blockIdx.x;
    __shared__ float red[256];
    const float* p = g_costpart + (n << 11);
    float s = 0.f;
    for (int k = threadIdx.x; k < P; k += 256) s += p[k];
    red[threadIdx.x] = s;
    __syncthreads();
    for (int s2 = 128; s2 > 0; s2 >>= 1) {
        if (threadIdx.x < s2) red[threadIdx.x] += red[threadIdx.x + s2];
        __syncthreads();
    }
    if (threadIdx.x == 0 && out_size > n) out[n] = red[0];
}

// ------------------------------------------------------------------ launch
extern "C" void kernel_launch(void* const* d_in, const int* in_sizes, int n_in,
                              void* d_out, int out_size) {
    const float* C  = (const float*)d_in[0];
    const float* mu = (const float*)d_in[1];
    const float* nu = (const float*)d_in[2];
    float* out = (float*)d_out;

    precompute_E<<<4096, 256>>>(C);
    sinkhorn_persist<<<NBLK, 256>>>(mu, nu);   // all 50 iterations, 1 launch
    final_pi<<<16384, 256>>>(C, out, out_size);
    cost_combine<<<8, 256>>>(out, out_size);
}

// round 9
// speedup vs baseline: 1.8033x; 1.0183x over previous
#include <cuda_runtime.h>
#include <cuda_fp16.h>
#include <math.h>

// Sinkhorn on GB300 — persistent kernel, register-resident wv, packed FFMA2.
//   Eh = exp(-C/eps) in fp16 (64 MB, L2-resident).
//   Lane owns 64 fixed columns; wv for them lives in 32 f32x2 registers,
//   reloaded once per iteration (16 LDG.128). Row dot + column accumulation
//   both use fma.rn.f32x2. No per-row LDS at all.

#define P 2048
#define NB 8
#define INV_EPS 10.0f
#define LOG_EPS 1e-8f
#define MAX_ITER 50
#define TOT 33554432           // NB * P * P
#define NBLK 128               // 8 batches x 16 row-blocks; co-resident

typedef unsigned long long ull;

__device__ __half g_Eh[TOT];
__device__ float g_wu[NB * P];
__device__ float g_wv[NB * P];
__device__ float g_bpart[NB * 16 * P];   // 1 MB block partials
__device__ float g_costpart[NB * P];

__device__ unsigned g_arrive;            // zero-init
__device__ volatile unsigned g_gen;

__device__ __forceinline__ float2 h2f(unsigned int u) {
    __half2 h = *reinterpret_cast<__half2*>(&u);
    return __half22float2(h);
}
__device__ __forceinline__ ull pk(float a, float b) {
    ull r; asm("mov.b64 %0, {%1, %2};" : "=l"(r) : "f"(a), "f"(b)); return r;
}
__device__ __forceinline__ void upk(float& a, float& b, ull r) {
    asm("mov.b64 {%0, %1}, %2;" : "=f"(a), "=f"(b) : "l"(r));
}
__device__ __forceinline__ ull ffma2(ull a, ull b, ull c) {
    ull d; asm("fma.rn.f32x2 %0, %1, %2, %3;" : "=l"(d) : "l"(a), "l"(b), "l"(c));
    return d;
}

// sense-reversing grid barrier; all NBLK blocks co-resident (1 block/SM).
__device__ __forceinline__ void grid_sync() {
    __syncthreads();
    if (threadIdx.x == 0) {
        unsigned g = g_gen;
        __threadfence();
        if (atomicAdd(&g_arrive, 1u) == NBLK - 1) {
            g_arrive = 0;
            __threadfence();
            g_gen = g + 1;
        } else {
            while (g_gen == g) __nanosleep(64);
        }
        __threadfence();
    }
    __syncthreads();
}

// ---------------------------------------------------------------- precompute
__global__ void precompute_E(const float* __restrict__ C) {
    size_t stride = (size_t)gridDim.x * blockDim.x;
    const float4* c4 = (const float4*)C;
    int4* e4 = (int4*)g_Eh;
    for (size_t k = (size_t)blockIdx.x * blockDim.x + threadIdx.x;
         k < (size_t)TOT / 8; k += stride) {
        float4 a = c4[2 * k], b = c4[2 * k + 1];
        __half2 h0 = __floats2half2_rn(expf(-a.x * INV_EPS), expf(-a.y * INV_EPS));
        __half2 h1 = __floats2half2_rn(expf(-a.z * INV_EPS), expf(-a.w * INV_EPS));
        __half2 h2 = __floats2half2_rn(expf(-b.x * INV_EPS), expf(-b.y * INV_EPS));
        __half2 h3 = __floats2half2_rn(expf(-b.z * INV_EPS), expf(-b.w * INV_EPS));
        int4 o;
        o.x = *reinterpret_cast<int*>(&h0);
        o.y = *reinterpret_cast<int*>(&h1);
        o.z = *reinterpret_cast<int*>(&h2);
        o.w = *reinterpret_cast<int*>(&h3);
        e4[k] = o;
    }
}

// --------------------------------------------------------- persistent kernel
// block = (n, rblk). 8 warps x 16 rows. lane owns cols 256c+8*lane+h.
__global__ void __launch_bounds__(256, 1)
sinkhorn_persist(const float* __restrict__ mu, const float* __restrict__ nu) {
    int n = blockIdx.x >> 4;
    int rblk = blockIdx.x & 15;
    int wid = threadIdx.x >> 5;
    int lane = threadIdx.x & 31;

    __shared__ float red[8][512];     // block-reduce staging
    __shared__ float mus[128];

    if (threadIdx.x < 128)
        mus[threadIdx.x] = mu[(n << 11) + rblk * 128 + threadIdx.x] + LOG_EPS;

    int gid = blockIdx.x * 256 + threadIdx.x;     // 0..32767
    float nuv = 0.f;
    if (gid < NB * P) {
        nuv = nu[gid] + LOG_EPS;
        g_wv[gid] = 1.0f;
    }
    grid_sync();

    const int4* Eb = (const int4*)(g_Eh + ((size_t)n << 22));
    const float4* wvb4 = (const float4*)(g_wv + (n << 11));
    int i0 = rblk * 128 + wid * 16;

    for (int it = 0; it < MAX_ITER; it++) {
        // reload lane's wv into registers (16 LDG.128)
        ull wv2[32];
#pragma unroll
        for (int c = 0; c < 8; c++) {
            float4 A = wvb4[64 * c + 2 * lane];
            float4 B = wvb4[64 * c + 2 * lane + 1];
            wv2[c * 4 + 0] = pk(A.x, A.y);
            wv2[c * 4 + 1] = pk(A.z, A.w);
            wv2[c * 4 + 2] = pk(B.x, B.y);
            wv2[c * 4 + 3] = pk(B.z, B.w);
        }

        ull acc2[32];
        ull z2 = pk(0.f, 0.f);
#pragma unroll
        for (int k = 0; k < 32; k++) acc2[k] = z2;

        for (int r = 0; r < 16; r++) {
            int i = i0 + r;
            const int4* e4 = Eb + ((size_t)i << 8);

            ull ef2[32];
#pragma unroll
            for (int c = 0; c < 8; c++) {
                int4 e = e4[c * 32 + lane];
                float2 f0 = h2f((unsigned)e.x);
                float2 f1 = h2f((unsigned)e.y);
                float2 f2 = h2f((unsigned)e.z);
                float2 f3 = h2f((unsigned)e.w);
                ef2[c * 4 + 0] = pk(f0.x, f0.y);
                ef2[c * 4 + 1] = pk(f1.x, f1.y);
                ef2[c * 4 + 2] = pk(f2.x, f2.y);
                ef2[c * 4 + 3] = pk(f3.x, f3.y);
            }

            // row dot: 32 FFMA2 in 4 chains
            ull sa = z2, sb = z2, sc = z2, sd = z2;
#pragma unroll
            for (int k = 0; k < 32; k += 4) {
                sa = ffma2(ef2[k + 0], wv2[k + 0], sa);
                sb = ffma2(ef2[k + 1], wv2[k + 1], sb);
                sc = ffma2(ef2[k + 2], wv2[k + 2], sc);
                sd = ffma2(ef2[k + 3], wv2[k + 3], sd);
            }
            float xa, xb, xc, xd, ya, yb, yc, yd;
            upk(xa, ya, sa); upk(xb, yb, sb);
            upk(xc, yc, sc); upk(xd, yd, sd);
            float s = ((xa + xb) + (xc + xd)) + ((ya + yb) + (yc + yd));
#pragma unroll
            for (int off = 16; off; off >>= 1)
                s += __shfl_xor_sync(0xffffffffu, s, off);

            float wu = mus[wid * 16 + r] / s;
            if (lane == 0) g_wu[(n << 11) + i] = wu;
            ull wu2 = pk(wu, wu);

            // column accumulation: 32 FFMA2 from the same ef2 registers
#pragma unroll
            for (int k = 0; k < 32; k++)
                acc2[k] = ffma2(ef2[k], wu2, acc2[k]);
        }

        // unpack acc, block-level reduce: 4 chunks of 512 columns
        float acc[64];
#pragma unroll
        for (int k = 0; k < 32; k++) upk(acc[2 * k], acc[2 * k + 1], acc2[k]);

        float* bp = g_bpart + ((size_t)(n * 16 + rblk) << 11);
#pragma unroll
        for (int chunk = 0; chunk < 4; chunk++) {
            __syncthreads();
#pragma unroll
            for (int cp = 0; cp < 2; cp++)
#pragma unroll
                for (int h = 0; h < 8; h++)
                    red[wid][cp * 256 + lane * 8 + h] = acc[(2 * chunk + cp) * 8 + h];
            __syncthreads();
#pragma unroll
            for (int t = threadIdx.x; t < 512; t += 256) {
                float v = 0.f;
#pragma unroll
                for (int w = 0; w < 8; w++) v += red[w][t];
                bp[chunk * 512 + t] = v;
            }
        }

        grid_sync();                               // all block partials visible

        // distributed combine: 1 thread per (n,j)
        if (gid < NB * P) {
            int nn = gid >> 11, j = gid & 2047;
            const float* pp = g_bpart + ((size_t)(nn * 16) << 11) + j;
            float t0 = 0.f, t1 = 0.f, t2 = 0.f, t3 = 0.f;
#pragma unroll
            for (int b = 0; b < 16; b += 4) {
                t0 += pp[(size_t)(b + 0) << 11];
                t1 += pp[(size_t)(b + 1) << 11];
                t2 += pp[(size_t)(b + 2) << 11];
                t3 += pp[(size_t)(b + 3) << 11];
            }
            g_wv[gid] = nuv / ((t0 + t1) + (t2 + t3));
        }

        grid_sync();                               // wv complete for next iter
    }
}

// ---------------------------------------------------------------- epilogue
__global__ void __launch_bounds__(256) final_pi(const float* __restrict__ C,
                                                float* __restrict__ out,
                                                int out_size) {
    int rowg = blockIdx.x;              // 0..16383
    int n = rowg >> 11, i = rowg & 2047;
    size_t base = ((size_t)n << 22) + ((size_t)i << 11);
    float wui = g_wu[(n << 11) + i];

    const int4* e4 = (const int4*)(g_Eh + base);
    const float4* c4 = (const float4*)(C + base);
    const float4* w4 = (const float4*)(g_wv + (n << 11));

    bool wpi = out_size >= 8 + TOT;
    bool wc  = out_size >= 8 + 2 * TOT;
    float4* pio = (float4*)(out + 8) + base / 4;
    float4* cco = (float4*)(out + 8 + (size_t)TOT) + base / 4;

    int t = threadIdx.x;
    int4 r = e4[t];
    float4 cA = c4[2 * t], cB = c4[2 * t + 1];
    float4 wA = w4[2 * t], wB = w4[2 * t + 1];
    float2 f0 = h2f((unsigned)r.x);
    float2 f1 = h2f((unsigned)r.y);
    float2 f2 = h2f((unsigned)r.z);
    float2 f3 = h2f((unsigned)r.w);
    float4 pA, pB;
    pA.x = f0.x * wui * wA.x;  pA.y = f0.y * wui * wA.y;
    pA.z = f1.x * wui * wA.z;  pA.w = f1.y * wui * wA.w;
    pB.x = f2.x * wui * wB.x;  pB.y = f2.y * wui * wB.y;
    pB.z = f3.x * wui * wB.z;  pB.w = f3.y * wui * wB.w;
    if (wpi) { pio[2 * t] = pA; pio[2 * t + 1] = pB; }
    if (wc)  { cco[2 * t] = cA; cco[2 * t + 1] = cB; }
    float cl = 0.f;
    cl = fmaf(pA.x, cA.x, fmaf(pA.y, cA.y, fmaf(pA.z, cA.z, fmaf(pA.w, cA.w, cl))));
    cl = fmaf(pB.x, cB.x, fmaf(pB.y, cB.y, fmaf(pB.z, cB.z, fmaf(pB.w, cB.w, cl))));

    __shared__ float red[256];
    red[t] = cl;
    __syncthreads();
    for (int s2 = 128; s2 > 0; s2 >>= 1) {
        if (t < s2) red[t] += red[t + s2];
        __syncthreads();
    }
    if (t == 0) g_costpart[rowg] = red[0];
}

__global__ void cost_combine(float* __restrict__ out, int out_size) {
    int n = blockIdx.x;
    __shared__ float red[256];
    const float* p = g_costpart + (n << 11);
    float s = 0.f;
    for (int k = threadIdx.x; k < P; k += 256) s += p[k];
    red[threadIdx.x] = s;
    __syncthreads();
    for (int s2 = 128; s2 > 0; s2 >>= 1) {
        if (threadIdx.x < s2) red[threadIdx.x] += red[threadIdx.x + s2];
        __syncthreads();
    }
    if (threadIdx.x == 0 && out_size > n) out[n] = red[0];
}

// ------------------------------------------------------------------ launch
extern "C" void kernel_launch(void* const* d_in, const int* in_sizes, int n_in,
                              void* d_out, int out_size) {
    const float* C  = (const float*)d_in[0];
    const float* mu = (const float*)d_in[1];
    const float* nu = (const float*)d_in[2];
    float* out = (float*)d_out;

    precompute_E<<<4096, 256>>>(C);
    sinkhorn_persist<<<NBLK, 256>>>(mu, nu);
    final_pi<<<16384, 256>>>(C, out, out_size);
    cost_combine<<<8, 256>>>(out, out_size);
}